// round 2
// baseline (speedup 1.0000x reference)
#include <cuda_runtime.h>
#include <stdint.h>

// Problem: BS=32, SEQ_LEN=4096, HIDDEN=1024
// inputs (metadata order):
//   d_in[0]: output_tokens_from_bert  float32  (32, 4096, 1024)
//   d_in[1]: attention_mask           int32    (32, 4096)
// output: float32 (32, 1024)
//
// out[b,e] = tokens[b, idx[b,e], e]
//   len[b]    = sum(mask[b,:])                   (mask is a monotone 1-prefix)
//   n_valid   = max(len-1, 1)
//   u[b,e]    = jax.random.uniform(key(42), (32,1024))
//               [partitionable threefry: bits[i] = b1^b2 of threefry((0,42), (0, i))]
//   idx       = min(trunc(u * float(n_valid)), n_valid-1)

#define BS 32
#define SEQ_LEN 4096
#define HIDDEN 1024

__device__ __forceinline__ uint32_t rotl32(uint32_t x, int d) {
    return (x << d) | (x >> (32 - d));
}

// JAX threefry2x32, 20 rounds, key = (0, 42)
__device__ __forceinline__ void threefry2x32_0_42(uint32_t x0, uint32_t x1,
                                                  uint32_t& o0, uint32_t& o1) {
    const uint32_t k0 = 0u;
    const uint32_t k1 = 42u;
    const uint32_t k2 = 0x1BD11BDAu ^ k0 ^ k1;
    uint32_t ks[3] = {k0, k1, k2};

    x0 += ks[0];
    x1 += ks[1];

    const int rotA[4] = {13, 15, 26, 6};
    const int rotB[4] = {17, 29, 16, 24};

#pragma unroll
    for (int blk = 0; blk < 5; ++blk) {
        const int* rots = (blk & 1) ? rotB : rotA;
#pragma unroll
        for (int r = 0; r < 4; ++r) {
            x0 += x1;
            x1 = rotl32(x1, rots[r]);
            x1 ^= x0;
        }
        x0 += ks[(blk + 1) % 3];
        x1 += ks[(blk + 2) % 3] + (uint32_t)(blk + 1);
    }
    o0 = x0;
    o1 = x1;
}

__global__ __launch_bounds__(1024, 1)
void condensed_embracement_kernel(const float* __restrict__ tokens,
                                  const int*   __restrict__ mask,
                                  float*       __restrict__ out) {
    const int b = blockIdx.x;     // batch row
    const int e = threadIdx.x;    // embedding column, 0..1023

    // ---- 1) Issue mask load early (int4: 1024 threads x 4 ints = 4096) ----
    const int4* m4 = reinterpret_cast<const int4*>(mask + (size_t)b * SEQ_LEN);
    int4 mv = __ldg(&m4[e]);

    // ---- 2) Threefry (partitionable mode) while the mask load is in flight ----
    // flat index into the (32*1024) uniform array; counter = (hi=0, lo=i)
    const uint32_t i = (uint32_t)(b * HIDDEN + e);
    uint32_t o0, o1;
    threefry2x32_0_42(0u, i, o0, o1);
    const uint32_t bits = o0 ^ o1;      // bit_width==32 partitionable: b1 ^ b2

    // uniform in [0,1): bitcast trick, identical to JAX
    float f = __uint_as_float((bits >> 9) | 0x3f800000u) - 1.0f;
    float u = fmaxf(0.0f, f);

    // ---- 3) Block-reduce the mask sum -> len ----
    int s = mv.x + mv.y + mv.z + mv.w;
#pragma unroll
    for (int off = 16; off > 0; off >>= 1)
        s += __shfl_down_sync(0xFFFFFFFFu, s, off);

    __shared__ int warp_sums[32];
    const int lane = e & 31;
    const int wid  = e >> 5;
    if (lane == 0) warp_sums[wid] = s;
    __syncthreads();

    __shared__ int s_len;
    if (wid == 0) {
        int v = warp_sums[lane];      // 32 warps -> 32 partials
#pragma unroll
        for (int off = 16; off > 0; off >>= 1)
            v += __shfl_down_sync(0xFFFFFFFFu, v, off);
        if (lane == 0) s_len = v;
    }
    __syncthreads();

    const int len     = s_len;
    const int n_valid = max(len - 1, 1);

    // ---- 4) Index + gather + store ----
    int idx = (int)(u * (float)n_valid);       // trunc toward zero == astype(int32)
    idx = min(idx, n_valid - 1);

    const float v = __ldg(&tokens[((size_t)b * SEQ_LEN + (size_t)idx) * HIDDEN + e]);
    out[b * HIDDEN + e] = v;
}

extern "C" void kernel_launch(void* const* d_in, const int* in_sizes, int n_in,
                              void* d_out, int out_size) {
    const float* tokens = (const float*)d_in[0];
    const int*   mask   = (const int*)d_in[1];
    float*       out    = (float*)d_out;

    condensed_embracement_kernel<<<BS, 1024>>>(tokens, mask, out);
}

// round 4
// speedup vs baseline: 1.0435x; 1.0435x over previous
#include <cuda_runtime.h>
#include <stdint.h>

// Problem: BS=32, SEQ_LEN=4096, HIDDEN=1024
// inputs (metadata order):
//   d_in[0]: output_tokens_from_bert  float32  (32, 4096, 1024)
//   d_in[1]: attention_mask           int32    (32, 4096)
// output: float32 (32, 1024)
//
// out[b,e] = tokens[b, idx[b,e], e]
//   len[b]    = sum(mask[b,:])                   (mask is a monotone 1-prefix)
//   n_valid   = max(len-1, 1)
//   u[b,e]    = jax.random.uniform(key(42), (32,1024))
//               [partitionable threefry: bits[i] = b1^b2 of threefry((0,42), (0, i))]
//   idx       = min(trunc(u * float(n_valid)), n_valid-1)
//
// R3: grid (32 rows x 4 column-slices) x 256 threads = 128 CTAs (~1/SM)
//     Each CTA redundantly reduces its mask row (4x int4/thread, MLP=4);
//     redundant reads L2-hit, so DRAM mask traffic is unchanged while the
//     gather is issued from ~128 SMs concurrently instead of 32.

#define BS 32
#define SEQ_LEN 4096
#define HIDDEN 1024
#define SLICES 4
#define TPB 256          // threads per block; SLICES*TPB == HIDDEN
#define INT4_PER_THREAD (SEQ_LEN / 4 / TPB)   // 4

__device__ __forceinline__ uint32_t rotl32(uint32_t x, int d) {
    return (x << d) | (x >> (32 - d));
}

// JAX threefry2x32, 20 rounds, key = (0, 42)
__device__ __forceinline__ void threefry2x32_0_42(uint32_t x0, uint32_t x1,
                                                  uint32_t& o0, uint32_t& o1) {
    const uint32_t k0 = 0u;
    const uint32_t k1 = 42u;
    const uint32_t k2 = 0x1BD11BDAu ^ k0 ^ k1;
    uint32_t ks[3] = {k0, k1, k2};

    x0 += ks[0];
    x1 += ks[1];

    const int rotA[4] = {13, 15, 26, 6};
    const int rotB[4] = {17, 29, 16, 24};

#pragma unroll
    for (int blk = 0; blk < 5; ++blk) {
        const int* rots = (blk & 1) ? rotB : rotA;
#pragma unroll
        for (int r = 0; r < 4; ++r) {
            x0 += x1;
            x1 = rotl32(x1, rots[r]);
            x1 ^= x0;
        }
        x0 += ks[(blk + 1) % 3];
        x1 += ks[(blk + 2) % 3] + (uint32_t)(blk + 1);
    }
    o0 = x0;
    o1 = x1;
}

__global__ __launch_bounds__(TPB, 1)
void condensed_embracement_kernel(const float* __restrict__ tokens,
                                  const int*   __restrict__ mask,
                                  float*       __restrict__ out) {
    const int b     = blockIdx.x;                 // batch row
    const int tid   = threadIdx.x;                // 0..255
    const int e     = blockIdx.y * TPB + tid;     // embedding column, 0..1023

    // ---- 1) Issue mask loads early: 4 x int4 per thread, MLP=4 ----
    const int4* m4 = reinterpret_cast<const int4*>(mask + (size_t)b * SEQ_LEN);
    int4 mv[INT4_PER_THREAD];
#pragma unroll
    for (int k = 0; k < INT4_PER_THREAD; ++k)
        mv[k] = __ldg(&m4[tid + k * TPB]);

    // ---- 2) Threefry (partitionable mode) while mask loads are in flight ----
    const uint32_t i = (uint32_t)(b * HIDDEN + e);
    uint32_t o0, o1;
    threefry2x32_0_42(0u, i, o0, o1);
    const uint32_t bits = o0 ^ o1;      // bit_width==32 partitionable: b1 ^ b2

    float f = __uint_as_float((bits >> 9) | 0x3f800000u) - 1.0f;
    float u = fmaxf(0.0f, f);

    // ---- 3) Block-reduce the mask sum -> len ----
    int s = 0;
#pragma unroll
    for (int k = 0; k < INT4_PER_THREAD; ++k)
        s += mv[k].x + mv[k].y + mv[k].z + mv[k].w;

#pragma unroll
    for (int off = 16; off > 0; off >>= 1)
        s += __shfl_down_sync(0xFFFFFFFFu, s, off);

    __shared__ int warp_sums[TPB / 32];
    const int lane = tid & 31;
    const int wid  = tid >> 5;
    if (lane == 0) warp_sums[wid] = s;
    __syncthreads();

    __shared__ int s_len;
    if (wid == 0) {
        int v = (lane < TPB / 32) ? warp_sums[lane] : 0;
#pragma unroll
        for (int off = 4; off > 0; off >>= 1)
            v += __shfl_down_sync(0xFFFFFFFFu, v, off);
        if (lane == 0) s_len = v;
    }
    __syncthreads();

    const int len     = s_len;
    const int n_valid = max(len - 1, 1);

    // ---- 4) Index + gather + store ----
    int idx = (int)(u * (float)n_valid);       // trunc toward zero == astype(int32)
    idx = min(idx, n_valid - 1);

    const float v = __ldg(&tokens[((size_t)b * SEQ_LEN + (size_t)idx) * HIDDEN + e]);
    out[b * HIDDEN + e] = v;
}

extern "C" void kernel_launch(void* const* d_in, const int* in_sizes, int n_in,
                              void* d_out, int out_size) {
    const float* tokens = (const float*)d_in[0];
    const int*   mask   = (const int*)d_in[1];
    float*       out    = (float*)d_out;

    dim3 grid(BS, SLICES);
    condensed_embracement_kernel<<<grid, TPB>>>(tokens, mask, out);
}